// round 13
// baseline (speedup 1.0000x reference)
#include <cuda_runtime.h>
#include <cuda_bf16.h>
#include <cstdint>

// ============================================================================
// MajFC, fully fused single kernel. Bit-plane majority formulation:
//   mismatch bits m_j = xb_j ^ wb_j (j = 0..2 within each 3-group)
//   clip(sum,-1,1) = 1 - 2*MAJ(m0,m1,m2);  out = 2304 - 4.5*T, T = #MAJ-groups.
// Rows stored as 3 bit-planes per 4-block supergroup (12 words x 8 = 96 words).
// Phase 1: cooperative pack. Device-wide spin barrier (grid sized for
// guaranteed co-residency). Phase 2: 512 full-K 16x32 tiles, direct output.
// ============================================================================

#define BROWS 256
#define CIN   3072
#define COUT  1024
#define KWP   96             // 3 planes x 32 block-words per row
#define NSG   8              // supergroups (12 words each)

#define NCTA  1184           // 148 SMs x 8 CTAs, 128 thr: co-resident by constr.
#define NWARP (NCTA * 4)

__device__ __align__(16) uint32_t g_Xb[BROWS * KWP];          // 96 KB
__device__ __align__(16) uint32_t g_Wb[COUT  * KWP];          // 384 KB
__device__ int g_sync;                                        // zero-init
__device__ int g_done;                                        // zero-init

__device__ __forceinline__ uint32_t maj3(uint32_t a, uint32_t b, uint32_t c) {
    uint32_t r;
    asm("lop3.b32 %0, %1, %2, %3, 0xE8;" : "=r"(r) : "r"(a), "r"(b), "r"(c));
    return r;
}

// ---------------------------------------------------------------------------
// Pack one 768-float segment (task) of one row into bit-plane layout.
// Lane i owns group (block*32 + i) of each of 8 blocks.
// ---------------------------------------------------------------------------
#define SEGS 4
#define PACK_TASKS ((BROWS + COUT) * SEGS)       // 5120

__device__ __forceinline__ void pack_task(int task, int lane,
                                          const float* __restrict__ x,
                                          const float* __restrict__ w) {
    int row = task >> 2, seg = task & 3;
    const float* src;
    uint32_t*    dst;
    if (row < BROWS) {
        src = x + (size_t)row * CIN;
        dst = g_Xb + (size_t)row * KWP;
    } else {
        src = w + (size_t)(row - BROWS) * CIN;
        dst = g_Wb + (size_t)(row - BROWS) * KWP;
    }
    const float* base = src + seg * 768 + lane * 3;

    unsigned c0[8], c1[8], c2[8];
#pragma unroll
    for (int b = 0; b < 8; b++) {
        const float* p = base + b * 96;
        c0[b] = p[0] > 0.f;
        c1[b] = p[1] > 0.f;
        c2[b] = p[2] > 0.f;
    }
    unsigned my = 0;
#pragma unroll
    for (int b = 0; b < 8; b++) {
        unsigned w0 = __ballot_sync(0xFFFFFFFFu, c0[b]);
        unsigned w1 = __ballot_sync(0xFFFFFFFFu, c1[b]);
        unsigned w2 = __ballot_sync(0xFFFFFFFFu, c2[b]);
        if (lane == b)      my = w0;
        if (lane == 8 + b)  my = w1;
        if (lane == 16 + b) my = w2;
    }
    if (lane < 24) {
        int j = lane >> 3, bl = lane & 7;           // plane, local block
        int gb = seg * 8 + bl;                      // global block 0..31
        dst[(gb >> 2) * 12 + j * 4 + (gb & 3)] = my;
    }
}

// ---------------------------------------------------------------------------
// Fused kernel. Phase 2: tiles 16(m) x 32(n), full K; 512 tiles over NCTA
// CTAs (bid < 512 compute, the rest exit after the barrier).
// SMEM pitch 12 words (48B): rows 16B-aligned; Ws read units 3*ni mod 8 =
// permutation (conflict-free); Xs reads broadcast within 8-lane groups.
// ---------------------------------------------------------------------------
#define TM 16
#define TN 32

__global__ void __launch_bounds__(128, 8)
maj_fused_kernel(const float* __restrict__ x, const float* __restrict__ w,
                 float* __restrict__ out) {
    __shared__ __align__(16) uint32_t Xs[TM][12];   // 768 B
    __shared__ __align__(16) uint32_t Ws[TN][12];   // 1536 B

    int tid  = threadIdx.x;
    int lane = tid & 31;
    int bid  = blockIdx.x;
    int gwarp = bid * 4 + (tid >> 5);

    // ---------------- Phase 1: cooperative pack ----------------
    for (int t = gwarp; t < PACK_TASKS; t += NWARP)
        pack_task(t, lane, x, w);

    // ---------------- Device-wide barrier (all CTAs resident) ----------------
    __threadfence();                       // release pack stores
    __syncthreads();
    if (tid == 0) {
        atomicAdd(&g_sync, 1);
        while (*(volatile int*)&g_sync < NCTA) __nanosleep(128);
    }
    __syncthreads();
    __threadfence();                       // acquire

    // ---------------- Phase 2: majority GEMM ----------------
    if (bid < 512) {
        int tm = bid >> 5, tn = bid & 31;       // 16 x 32 tile grid
        int m0 = tm * TM, n0 = tn * TN;
        int mi = tid >> 3;                      // 0..15 -> one m row
        int ni = tid & 7;                       // 0..7  -> n cols ni+8c

        int acc0 = 0, acc1 = 0, acc2 = 0, acc3 = 0;
#pragma unroll
        for (int s = 0; s < NSG; s++) {
            __syncthreads();
            // Stage 48 rows x 3 uint4 = 144 uint4 over 128 threads.
#pragma unroll
            for (int p = 0; p < 2; p++) {
                int idx = p * 128 + tid;
                if (idx < 144) {
                    uint4 v;
                    uint32_t* d;
                    if (idx < 48) {
                        int r = idx / 3, q = idx - r * 3;
                        v = *reinterpret_cast<const uint4*>(
                            &g_Xb[(size_t)(m0 + r) * KWP + s * 12 + q * 4]);
                        d = &Xs[r][q * 4];
                    } else {
                        int u = idx - 48;
                        int r = u / 3, q = u - r * 3;
                        v = *reinterpret_cast<const uint4*>(
                            &g_Wb[(size_t)(n0 + r) * KWP + s * 12 + q * 4]);
                        d = &Ws[r][q * 4];
                    }
                    *reinterpret_cast<uint4*>(d) = v;
                }
            }
            __syncthreads();

            uint4 x0 = *reinterpret_cast<const uint4*>(&Xs[mi][0]);
            uint4 x1 = *reinterpret_cast<const uint4*>(&Xs[mi][4]);
            uint4 x2 = *reinterpret_cast<const uint4*>(&Xs[mi][8]);
            const uint32_t* xp0 = reinterpret_cast<const uint32_t*>(&x0);
            const uint32_t* xp1 = reinterpret_cast<const uint32_t*>(&x1);
            const uint32_t* xp2 = reinterpret_cast<const uint32_t*>(&x2);
#pragma unroll
            for (int c = 0; c < 4; c++) {
                uint4 w0 = *reinterpret_cast<const uint4*>(&Ws[ni + c * 8][0]);
                uint4 w1 = *reinterpret_cast<const uint4*>(&Ws[ni + c * 8][4]);
                uint4 w2 = *reinterpret_cast<const uint4*>(&Ws[ni + c * 8][8]);
                const uint32_t* wp0 = reinterpret_cast<const uint32_t*>(&w0);
                const uint32_t* wp1 = reinterpret_cast<const uint32_t*>(&w1);
                const uint32_t* wp2 = reinterpret_cast<const uint32_t*>(&w2);
                int a = 0;
#pragma unroll
                for (int e = 0; e < 4; e++)
                    a += __popc(maj3(xp0[e] ^ wp0[e],
                                     xp1[e] ^ wp1[e],
                                     xp2[e] ^ wp2[e]));
                if (c == 0) acc0 += a;
                else if (c == 1) acc1 += a;
                else if (c == 2) acc2 += a;
                else acc3 += a;
            }
        }

        // out = 2.25 * (1024 - 2T) = 2304 - 4.5*T
        float* o = out + (size_t)(m0 + mi) * COUT + n0 + ni;
        o[0]  = 2304.0f - 4.5f * (float)acc0;
        o[8]  = 2304.0f - 4.5f * (float)acc1;
        o[16] = 2304.0f - 4.5f * (float)acc2;
        o[24] = 2304.0f - 4.5f * (float)acc3;
    }

    // ---------------- reset counters for next graph replay ----------------
    __syncthreads();
    if (tid == 0) {
        __threadfence();
        int d = atomicAdd(&g_done, 1);
        if (d == NCTA - 1) {               // last CTA on the device
            g_sync = 0;
            g_done = 0;
            __threadfence();
        }
    }
}

// ---------------------------------------------------------------------------
extern "C" void kernel_launch(void* const* d_in, const int* in_sizes, int n_in,
                              void* d_out, int out_size) {
    const float* x = (const float*)d_in[0];   // [256, 3072]
    const float* w = (const float*)d_in[1];   // [1024, 3072]
    float* out = (float*)d_out;               // [256, 1024] float32

    maj_fused_kernel<<<NCTA, 128>>>(x, w, out);
}

// round 14
// speedup vs baseline: 1.7068x; 1.7068x over previous
#include <cuda_runtime.h>
#include <cuda_bf16.h>
#include <cstdint>

// ============================================================================
// MajFC via bit-plane majority:
//   mismatch bits m_j = xb_j ^ wb_j  ->  clip(sum,-1,1) = 1 - 2*MAJ(m0,m1,m2)
//   out = 2304 - 4.5*T,  T = #groups with MAJ = 1.
// Row layout: 8 supergroups x 12 words (3 planes x 4 block-words), K = 96.
// R14: full-K GEMM (512 tiles, direct output, NO atomics/fences) with
// cp.async double-buffered supergroup staging to overlap LDG with compute.
// ============================================================================

#define BROWS 256
#define CIN   3072
#define COUT  1024
#define KWP   96
#define NSG   8

__device__ __align__(16) uint32_t g_Xb[BROWS * KWP];          // 96 KB
__device__ __align__(16) uint32_t g_Wb[COUT  * KWP];          // 384 KB

__device__ __forceinline__ uint32_t maj3(uint32_t a, uint32_t b, uint32_t c) {
    uint32_t r;
    asm("lop3.b32 %0, %1, %2, %3, 0xE8;" : "=r"(r) : "r"(a), "r"(b), "r"(c));
    return r;
}

// ---------------------------------------------------------------------------
// Pack (R12): one warp = 768 floats (256 groups = 8 blocks) of one row.
// ---------------------------------------------------------------------------
#define SEGS 4
#define PACK_TASKS ((BROWS + COUT) * SEGS)       // 5120 warps

__global__ void __launch_bounds__(256) pack_kernel(const float* __restrict__ x,
                                                   const float* __restrict__ w) {
    int task = (blockIdx.x * blockDim.x + threadIdx.x) >> 5;
    int lane = threadIdx.x & 31;
    int row = task >> 2, seg = task & 3;

    const float* src;
    uint32_t*    dst;
    if (row < BROWS) {
        src = x + (size_t)row * CIN;
        dst = g_Xb + (size_t)row * KWP;
    } else {
        src = w + (size_t)(row - BROWS) * CIN;
        dst = g_Wb + (size_t)(row - BROWS) * KWP;
    }
    const float* base = src + seg * 768 + lane * 3;

    unsigned c0[8], c1[8], c2[8];
#pragma unroll
    for (int b = 0; b < 8; b++) {
        const float* p = base + b * 96;
        c0[b] = p[0] > 0.f;
        c1[b] = p[1] > 0.f;
        c2[b] = p[2] > 0.f;
    }
    unsigned my = 0;
#pragma unroll
    for (int b = 0; b < 8; b++) {
        unsigned w0 = __ballot_sync(0xFFFFFFFFu, c0[b]);
        unsigned w1 = __ballot_sync(0xFFFFFFFFu, c1[b]);
        unsigned w2 = __ballot_sync(0xFFFFFFFFu, c2[b]);
        if (lane == b)      my = w0;
        if (lane == 8 + b)  my = w1;
        if (lane == 16 + b) my = w2;
    }
    if (lane < 24) {
        int j = lane >> 3, bl = lane & 7;
        int gb = seg * 8 + bl;
        dst[(gb >> 2) * 12 + j * 4 + (gb & 3)] = my;
    }
}

// ---------------------------------------------------------------------------
// cp.async helpers (sm_80+ baseline PTX; fine on compute_103).
// ---------------------------------------------------------------------------
__device__ __forceinline__ void cp16(uint32_t smem, const void* gmem) {
    asm volatile("cp.async.cg.shared.global [%0], [%1], 16;"
                 :: "r"(smem), "l"(gmem));
}
__device__ __forceinline__ void cp_commit() {
    asm volatile("cp.async.commit_group;");
}
template <int N>
__device__ __forceinline__ void cp_wait() {
    asm volatile("cp.async.wait_group %0;" :: "n"(N));
}

// ---------------------------------------------------------------------------
// Full-K majority GEMM. Tile 16(m) x 32(n), 128 threads, grid = 512.
// Double-buffered supergroups: buf[b] = 48 rows (16 X + 32 W) x 12 words.
// Pitch 12 words (48B): 16B-aligned rows; W compute reads conflict-free
// (3*(16+ni+8c) mod 8 = 3*ni mod 8 = permutation); X reads phase-broadcast.
// ---------------------------------------------------------------------------
#define TM 16
#define TN 32

__global__ void __launch_bounds__(128) maj_gemm_kernel(float* __restrict__ out) {
    __shared__ __align__(16) uint32_t buf[2][48][12];   // 4.5 KB

    int tid = threadIdx.x;
    int bid = blockIdx.x;
    int m0 = (bid >> 5) * TM;             // 16 m-tiles
    int n0 = (bid & 31) * TN;             // 32 n-tiles
    int mi = tid >> 3;                    // 0..15 -> one m row
    int ni = tid & 7;                     // 0..7  -> n cols ni + 8c

    // Per-thread staging assignment (144 uint4 over 128 threads: 1-2 each).
    // idx < 48: X row idx/3, plane-quad idx%3 ; else W row (idx-48)/3.
    const uint32_t* gsrc0;
    const uint32_t* gsrc1 = nullptr;
    int soff0, soff1 = 0;
    {
        int idx = tid;
        int r = idx / 3, q = idx - r * 3;
        if (idx < 48) gsrc0 = &g_Xb[(size_t)(m0 + r) * KWP + q * 4];
        else { int u = idx - 48; r = u / 3; q = u - r * 3;
               gsrc0 = &g_Wb[(size_t)(n0 + r) * KWP + q * 4];
               soff0 = (16 + r) * 12 + q * 4; }
        if (idx < 48) soff0 = r * 12 + q * 4;
        if (tid < 16) {
            int u = 128 + tid - 48;       // idx 128..143 -> W rows
            r = u / 3; q = u - r * 3;
            gsrc1 = &g_Wb[(size_t)(n0 + r) * KWP + q * 4];
            soff1 = (16 + r) * 12 + q * 4;
        }
    }
    uint32_t sbase = (uint32_t)__cvta_generic_to_shared(&buf[0][0][0]);
    const uint32_t BUFB = 48 * 12 * 4;    // bytes per buffer

    // Prologue: stage supergroup 0 into buf[0].
    cp16(sbase + soff0 * 4, gsrc0);
    if (tid < 16) cp16(sbase + soff1 * 4, gsrc1);
    cp_commit();

    int acc0 = 0, acc1 = 0, acc2 = 0, acc3 = 0;

#pragma unroll
    for (int s = 0; s < NSG; s++) {
        // Stage s+1 into the other buffer while s is in flight / computing.
        if (s < NSG - 1) {
            uint32_t sb = sbase + ((s + 1) & 1) * BUFB;
            cp16(sb + soff0 * 4, gsrc0 + (s + 1) * 12);
            if (tid < 16) cp16(sb + soff1 * 4, gsrc1 + (s + 1) * 12);
            cp_commit();
            cp_wait<1>();                 // buffer s complete
        } else {
            cp_wait<0>();
        }
        __syncthreads();

        const uint32_t (*B)[12] = buf[s & 1];
        uint4 x0 = *reinterpret_cast<const uint4*>(&B[mi][0]);
        uint4 x1 = *reinterpret_cast<const uint4*>(&B[mi][4]);
        uint4 x2 = *reinterpret_cast<const uint4*>(&B[mi][8]);
        const uint32_t* xp0 = reinterpret_cast<const uint32_t*>(&x0);
        const uint32_t* xp1 = reinterpret_cast<const uint32_t*>(&x1);
        const uint32_t* xp2 = reinterpret_cast<const uint32_t*>(&x2);
#pragma unroll
        for (int c = 0; c < 4; c++) {
            const uint32_t* wr = &B[16 + ni + c * 8][0];
            uint4 w0 = *reinterpret_cast<const uint4*>(wr);
            uint4 w1 = *reinterpret_cast<const uint4*>(wr + 4);
            uint4 w2 = *reinterpret_cast<const uint4*>(wr + 8);
            const uint32_t* wp0 = reinterpret_cast<const uint32_t*>(&w0);
            const uint32_t* wp1 = reinterpret_cast<const uint32_t*>(&w1);
            const uint32_t* wp2 = reinterpret_cast<const uint32_t*>(&w2);
            int a = 0;
#pragma unroll
            for (int e = 0; e < 4; e++)
                a += __popc(maj3(xp0[e] ^ wp0[e],
                                 xp1[e] ^ wp1[e],
                                 xp2[e] ^ wp2[e]));
            if      (c == 0) acc0 += a;
            else if (c == 1) acc1 += a;
            else if (c == 2) acc2 += a;
            else             acc3 += a;
        }
        __syncthreads();                  // done reading buf[s&1] before reuse
    }

    // out = 2.25 * (1024 - 2T) = 2304 - 4.5*T   (direct store, no partials)
    float* o = out + (size_t)(m0 + mi) * COUT + n0 + ni;
    o[0]  = 2304.0f - 4.5f * (float)acc0;
    o[8]  = 2304.0f - 4.5f * (float)acc1;
    o[16] = 2304.0f - 4.5f * (float)acc2;
    o[24] = 2304.0f - 4.5f * (float)acc3;
}

// ---------------------------------------------------------------------------
extern "C" void kernel_launch(void* const* d_in, const int* in_sizes, int n_in,
                              void* d_out, int out_size) {
    const float* x = (const float*)d_in[0];   // [256, 3072]
    const float* w = (const float*)d_in[1];   // [1024, 3072]
    float* out = (float*)d_out;               // [256, 1024] float32

    pack_kernel<<<PACK_TASKS * 32 / 256, 256>>>(x, w);
    maj_gemm_kernel<<<512, 128>>>(out);
}